// round 1
// baseline (speedup 1.0000x reference)
#include <cuda_runtime.h>
#include <math.h>

#define B_    4
#define NPTS  8192
#define KNN   9
#define TPB   256
#define NPOINTS (B_*NPTS)        // 32768
#define NROWS   (NPOINTS*KNN)    // 294912
#define NB1     (NPOINTS/TPB)    // 128
#define NB3     (NROWS/TPB)      // 1152
#define EPS_BN  1e-5f

// ---- scratch (static device memory; no allocations) ----
__device__ float g_h1[(size_t)NROWS*10];
__device__ float g_h2[(size_t)NROWS*10];
__device__ float g_part1[NB1*20];
__device__ float g_part2[NB3*20];
__device__ float g_coef1[20];   // [0..9]=a, [10..19]=c   (h*a+c == g*(h-mu)*invstd+be)
__device__ float g_coef2[20];

// =====================================================================
// Kernel 1: kNN (top-10, stable ties) + angular features + GEMM1 + stats
// =====================================================================
__global__ void __launch_bounds__(TPB) k_knn_feat(const float* __restrict__ x,
                                                  const float* __restrict__ W1,
                                                  const float* __restrict__ b1)
{
    extern __shared__ unsigned char smem_raw[];
    float4* sp   = (float4*)smem_raw;
    float*  sW1  = (float*)(smem_raw + NPTS*sizeof(float4));   // 70
    float*  sB1  = sW1 + 70;                                   // 10
    float*  sRed = sB1 + 10;                                   // 8*20

    const int b   = blockIdx.x / (NPTS/TPB);
    const int n   = (blockIdx.x % (NPTS/TPB)) * TPB + threadIdx.x;  // point within batch
    const float* xb = x + (size_t)b*NPTS*3;

    for (int i = threadIdx.x; i < NPTS; i += TPB) {
        float px = xb[3*i+0], py = xb[3*i+1], pz = xb[3*i+2];
        sp[i] = make_float4(px, py, pz, px*px + py*py + pz*pz);
    }
    if (threadIdx.x < 70) sW1[threadIdx.x] = W1[threadIdx.x];
    if (threadIdx.x < 10) sB1[threadIdx.x] = b1[threadIdx.x];
    __syncthreads();

    const float4 q = sp[n];
    const float qx2 = 2.f*q.x, qy2 = 2.f*q.y, qz2 = 2.f*q.z;

    // s_m = |p|^2 - 2 q.p  == d2 - |q|^2  (same ordering as reference d2)
    float s[KNN+1]; int id[KNN+1];
    #pragma unroll
    for (int j = 0; j <= KNN; j++) { s[j] = 3.4e38f; id[j] = -1; }

    #pragma unroll 4
    for (int m = 0; m < NPTS; m++) {
        float4 p = sp[m];
        float d = p.w;
        d = fmaf(-p.x, qx2, d);
        d = fmaf(-p.y, qy2, d);
        d = fmaf(-p.z, qz2, d);
        if (d < s[KNN]) {                 // strict < : stable like lax.top_k
            s[KNN] = d; id[KNN] = m;
            #pragma unroll
            for (int j = KNN-1; j >= 0; j--) {
                if (s[j+1] < s[j]) {
                    float ts = s[j];  s[j] = s[j+1];  s[j+1] = ts;
                    int   ti = id[j]; id[j] = id[j+1]; id[j+1] = ti;
                }
            }
        }
    }

    // neighbors 1..9 (entry 0 is self), relative vectors + angle
    float rx[KNN], ry[KNN], rz[KNN], ph[KNN];
    #pragma unroll
    for (int j = 0; j < KNN; j++) {
        float4 p = sp[id[j+1]];
        rx[j] = p.x - q.x; ry[j] = p.y - q.y; rz[j] = p.z - q.z;
        ph[j] = atan2f(ry[j], rx[j]);
    }

    // stable ascending sort by phi (adjacent-exchange bubble network, strict <)
    #pragma unroll
    for (int pass = 0; pass < KNN-1; pass++) {
        #pragma unroll
        for (int j = 0; j < KNN-1; j++) {
            if (j < KNN-1-pass) {
                if (ph[j+1] < ph[j]) {
                    float t;
                    t = ph[j]; ph[j] = ph[j+1]; ph[j+1] = t;
                    t = rx[j]; rx[j] = rx[j+1]; rx[j+1] = t;
                    t = ry[j]; ry[j] = ry[j+1]; ry[j+1] = t;
                    t = rz[j]; rz[j] = rz[j+1]; rz[j+1] = t;
                }
            }
        }
    }

    float sum[10], sq[10];
    #pragma unroll
    for (int c = 0; c < 10; c++) { sum[c] = 0.f; sq[c] = 0.f; }

    float sgn = 1.f;
    const size_t rowbase = ((size_t)(b*NPTS + n) * KNN) * 10;

    #pragma unroll
    for (int i = 0; i < KNN; i++) {
        const int i2 = (i+1) % KNN;
        float v1x = rx[i],  v1y = ry[i],  v1z = rz[i];
        float v2x = rx[i2], v2y = ry[i2], v2z = rz[i2];
        float cx = 0.5f*(v1x+v2x), cy = 0.5f*(v1y+v2y), cz = 0.5f*(v1z+v2z);
        float nx = v1y*v2z - v1z*v2y;
        float ny = v1z*v2x - v1x*v2z;
        float nz = v1x*v2y - v1y*v2x;
        float nrm = sqrtf(nx*nx + ny*ny + nz*nz);
        float inv = 1.f/(nrm + 1e-6f);
        nx *= inv; ny *= inv; nz *= inv;
        if (i == 0) sgn = (nx > 0.f) ? 1.f : -1.f;
        nx *= sgn; ny *= sgn; nz *= sgn;
        float pos = (nx*cx + ny*cy + nz*cz) * 0.57735026918962576f; // 1/sqrt(3)

        float f[7] = {cx, cy, cz, nx, ny, nz, pos};
        #pragma unroll
        for (int c = 0; c < 10; c++) {
            float h = sB1[c];
            #pragma unroll
            for (int ff = 0; ff < 7; ff++) h = fmaf(f[ff], sW1[ff*10 + c], h);
            g_h1[rowbase + i*10 + c] = h;
            sum[c] += h;
            sq[c]  = fmaf(h, h, sq[c]);
        }
    }

    // warp reduce -> per-warp smem -> per-block partials
    #pragma unroll
    for (int c = 0; c < 10; c++) {
        #pragma unroll
        for (int o = 16; o > 0; o >>= 1) {
            sum[c] += __shfl_down_sync(0xffffffffu, sum[c], o);
            sq[c]  += __shfl_down_sync(0xffffffffu, sq[c],  o);
        }
    }
    const int warp = threadIdx.x >> 5, lane = threadIdx.x & 31;
    if (lane == 0) {
        #pragma unroll
        for (int c = 0; c < 10; c++) {
            sRed[warp*20 + c]      = sum[c];
            sRed[warp*20 + 10 + c] = sq[c];
        }
    }
    __syncthreads();
    if (threadIdx.x < 20) {
        float t = 0.f;
        #pragma unroll
        for (int w = 0; w < TPB/32; w++) t += sRed[w*20 + threadIdx.x];
        g_part1[blockIdx.x*20 + threadIdx.x] = t;
    }
}

// =====================================================================
// Finalize BN stats layer 1
// =====================================================================
__global__ void k_fin1(const float* __restrict__ g1, const float* __restrict__ be1)
{
    int c = threadIdx.x;
    if (c < 10) {
        float sum = 0.f, sq = 0.f;
        for (int k = 0; k < NB1; k++) { sum += g_part1[k*20 + c]; sq += g_part1[k*20 + 10 + c]; }
        float mu  = sum / (float)NROWS;
        float var = sq / (float)NROWS - mu*mu;
        float a   = g1[c] * rsqrtf(var + EPS_BN);
        g_coef1[c]      = a;
        g_coef1[10 + c] = be1[c] - mu*a;
    }
}

// =====================================================================
// Kernel 3: BN1 + relu + GEMM2 + stats2
// =====================================================================
__global__ void __launch_bounds__(TPB) k_mlp2(const float* __restrict__ W2,
                                              const float* __restrict__ b2)
{
    __shared__ float sW2[100], sB2[10], sA[10], sC[10], sRed[(TPB/32)*20];
    const int t = threadIdx.x;
    if (t < 100) sW2[t] = W2[t];
    if (t < 10) { sB2[t] = b2[t]; sA[t] = g_coef1[t]; sC[t] = g_coef1[10+t]; }
    __syncthreads();

    const size_t row = (size_t)blockIdx.x*TPB + t;
    const float* src = g_h1 + row*10;

    float h[10];
    #pragma unroll
    for (int c = 0; c < 10; c++) h[c] = fmaxf(fmaf(src[c], sA[c], sC[c]), 0.f);

    float sum[10], sq[10];
    float* dst = g_h2 + row*10;
    #pragma unroll
    for (int c2 = 0; c2 < 10; c2++) {
        float z = sB2[c2];
        #pragma unroll
        for (int c = 0; c < 10; c++) z = fmaf(h[c], sW2[c*10 + c2], z);
        dst[c2] = z;
        sum[c2] = z;
        sq[c2]  = z*z;
    }

    #pragma unroll
    for (int c = 0; c < 10; c++) {
        #pragma unroll
        for (int o = 16; o > 0; o >>= 1) {
            sum[c] += __shfl_down_sync(0xffffffffu, sum[c], o);
            sq[c]  += __shfl_down_sync(0xffffffffu, sq[c],  o);
        }
    }
    const int warp = t >> 5, lane = t & 31;
    if (lane == 0) {
        #pragma unroll
        for (int c = 0; c < 10; c++) {
            sRed[warp*20 + c]      = sum[c];
            sRed[warp*20 + 10 + c] = sq[c];
        }
    }
    __syncthreads();
    if (t < 20) {
        float acc = 0.f;
        #pragma unroll
        for (int w = 0; w < TPB/32; w++) acc += sRed[w*20 + t];
        g_part2[blockIdx.x*20 + t] = acc;
    }
}

// =====================================================================
// Finalize BN stats layer 2
// =====================================================================
__global__ void k_fin2(const float* __restrict__ g2, const float* __restrict__ be2)
{
    int c = threadIdx.x;
    if (c < 10) {
        float sum = 0.f, sq = 0.f;
        for (int k = 0; k < NB3; k++) { sum += g_part2[k*20 + c]; sq += g_part2[k*20 + 10 + c]; }
        float mu  = sum / (float)NROWS;
        float var = sq / (float)NROWS - mu*mu;
        float a   = g2[c] * rsqrtf(var + EPS_BN);
        g_coef2[c]      = a;
        g_coef2[10 + c] = be2[c] - mu*a;
    }
}

// =====================================================================
// Kernel 5: BN2 + relu + max over k
// =====================================================================
__global__ void __launch_bounds__(TPB) k_out(float* __restrict__ out)
{
    __shared__ float sA[10], sC[10];
    if (threadIdx.x < 10) { sA[threadIdx.x] = g_coef2[threadIdx.x]; sC[threadIdx.x] = g_coef2[10+threadIdx.x]; }
    __syncthreads();

    const size_t p = (size_t)blockIdx.x*TPB + threadIdx.x;    // global point
    const float* src = g_h2 + p*KNN*10;

    float mx[10];
    #pragma unroll
    for (int c = 0; c < 10; c++) mx[c] = 0.f;   // relu outputs are >= 0

    #pragma unroll
    for (int i = 0; i < KNN; i++) {
        #pragma unroll
        for (int c = 0; c < 10; c++) {
            float v = fmaxf(fmaf(src[i*10 + c], sA[c], sC[c]), 0.f);
            mx[c] = fmaxf(mx[c], v);
        }
    }
    float* o = out + p*10;
    #pragma unroll
    for (int c = 0; c < 10; c++) o[c] = mx[c];
}

// =====================================================================
extern "C" void kernel_launch(void* const* d_in, const int* in_sizes, int n_in,
                              void* d_out, int out_size)
{
    const float* x   = (const float*)d_in[0];
    const float* W1  = (const float*)d_in[1];
    const float* b1  = (const float*)d_in[2];
    const float* g1  = (const float*)d_in[3];
    const float* be1 = (const float*)d_in[4];
    const float* W2  = (const float*)d_in[5];
    const float* b2  = (const float*)d_in[6];
    const float* g2  = (const float*)d_in[7];
    const float* be2 = (const float*)d_in[8];
    float* out = (float*)d_out;

    const size_t smem1 = (size_t)NPTS*sizeof(float4) + (70 + 10 + (TPB/32)*20)*sizeof(float);
    cudaFuncSetAttribute(k_knn_feat, cudaFuncAttributeMaxDynamicSharedMemorySize, (int)smem1);

    k_knn_feat<<<NB1, TPB, smem1>>>(x, W1, b1);
    k_fin1<<<1, 32>>>(g1, be1);
    k_mlp2<<<NB3, TPB>>>(W2, b2);
    k_fin2<<<1, 32>>>(g2, be2);
    k_out<<<NPOINTS/TPB, TPB>>>(out);
}

// round 2
// speedup vs baseline: 1.1206x; 1.1206x over previous
#include <cuda_runtime.h>
#include <math.h>

#define B_    4
#define NPTS  8192
#define KNN   9
#define TPB   256
#define NPOINTS (B_*NPTS)        // 32768
#define NROWS   (NPOINTS*KNN)    // 294912
#define NB1     (NPOINTS/TPB)    // 128
#define NB3     (NROWS/TPB)      // 1152
#define EPS_BN  1e-5f

// ---- scratch (static device memory; no allocations) ----
__device__ float g_h1[(size_t)NROWS*10];
__device__ float g_h2[(size_t)NROWS*10];
__device__ float g_part1[NB1*20];
__device__ float g_part2[NB3*20];
__device__ float g_coef1[20];   // [0..9]=a, [10..19]=c   (h*a+c == g*(h-mu)*invstd+be)
__device__ float g_coef2[20];

// =====================================================================
// Kernel 1: kNN (top-10, stable ties) + angular features + GEMM1 + stats
// =====================================================================
__global__ void __launch_bounds__(TPB) k_knn_feat(const float* __restrict__ x,
                                                  const float* __restrict__ W1,
                                                  const float* __restrict__ b1)
{
    extern __shared__ unsigned char smem_raw[];
    float4* sp   = (float4*)smem_raw;
    float*  sW1  = (float*)(smem_raw + NPTS*sizeof(float4));   // 70
    float*  sB1  = sW1 + 70;                                   // 10
    float*  sRed = sB1 + 10;                                   // 8*20

    const int b   = blockIdx.x / (NPTS/TPB);
    const int n   = (blockIdx.x % (NPTS/TPB)) * TPB + threadIdx.x;  // point within batch
    const float* xb = x + (size_t)b*NPTS*3;

    for (int i = threadIdx.x; i < NPTS; i += TPB) {
        float px = xb[3*i+0], py = xb[3*i+1], pz = xb[3*i+2];
        sp[i] = make_float4(px, py, pz, px*px + py*py + pz*pz);
    }
    if (threadIdx.x < 70) sW1[threadIdx.x] = W1[threadIdx.x];
    if (threadIdx.x < 10) sB1[threadIdx.x] = b1[threadIdx.x];
    __syncthreads();

    const float4 q = sp[n];
    const float qx2 = 2.f*q.x, qy2 = 2.f*q.y, qz2 = 2.f*q.z;

    // s_m = |p|^2 - 2 q.p  == d2 - |q|^2  (same ordering as reference d2)
    float s[KNN+1]; int id[KNN+1];
    #pragma unroll
    for (int j = 0; j <= KNN; j++) { s[j] = 3.4e38f; id[j] = -1; }

    #pragma unroll 1
    for (int m0 = 0; m0 < NPTS; m0 += 8) {
        // 8 distances, branch-free
        float d[8];
        #pragma unroll
        for (int u = 0; u < 8; u++) {
            float4 p = sp[m0 + u];
            float t0 = fmaf(-p.x, qx2, p.w);
            float t1 = fmaf(-p.y, qy2, t0);
            d[u] = fmaf(-p.z, qz2, t1);
        }
        // single rarely-taken test per group of 8
        float mn = fminf(fminf(fminf(d[0],d[1]), fminf(d[2],d[3])),
                         fminf(fminf(d[4],d[5]), fminf(d[6],d[7])));
        if (mn < s[KNN]) {
            #pragma unroll
            for (int u = 0; u < 8; u++) {
                if (d[u] < s[KNN]) {          // strict < : stable like lax.top_k
                    s[KNN] = d[u]; id[KNN] = m0 + u;
                    #pragma unroll
                    for (int j = KNN-1; j >= 0; j--) {
                        if (s[j+1] < s[j]) {
                            float ts = s[j];  s[j] = s[j+1];  s[j+1] = ts;
                            int   ti = id[j]; id[j] = id[j+1]; id[j+1] = ti;
                        }
                    }
                }
            }
        }
    }

    // neighbors 1..9 (entry 0 is self), relative vectors + angle
    float rx[KNN], ry[KNN], rz[KNN], ph[KNN];
    #pragma unroll
    for (int j = 0; j < KNN; j++) {
        float4 p = sp[id[j+1]];
        rx[j] = p.x - q.x; ry[j] = p.y - q.y; rz[j] = p.z - q.z;
        ph[j] = atan2f(ry[j], rx[j]);
    }

    // stable ascending sort by phi (adjacent-exchange bubble network, strict <)
    #pragma unroll
    for (int pass = 0; pass < KNN-1; pass++) {
        #pragma unroll
        for (int j = 0; j < KNN-1; j++) {
            if (j < KNN-1-pass) {
                if (ph[j+1] < ph[j]) {
                    float t;
                    t = ph[j]; ph[j] = ph[j+1]; ph[j+1] = t;
                    t = rx[j]; rx[j] = rx[j+1]; rx[j+1] = t;
                    t = ry[j]; ry[j] = ry[j+1]; ry[j+1] = t;
                    t = rz[j]; rz[j] = rz[j+1]; rz[j+1] = t;
                }
            }
        }
    }

    float sum[10], sq[10];
    #pragma unroll
    for (int c = 0; c < 10; c++) { sum[c] = 0.f; sq[c] = 0.f; }

    float sgn = 1.f;
    const size_t rowbase = ((size_t)(b*NPTS + n) * KNN) * 10;

    #pragma unroll
    for (int i = 0; i < KNN; i++) {
        const int i2 = (i+1) % KNN;
        float v1x = rx[i],  v1y = ry[i],  v1z = rz[i];
        float v2x = rx[i2], v2y = ry[i2], v2z = rz[i2];
        float cx = 0.5f*(v1x+v2x), cy = 0.5f*(v1y+v2y), cz = 0.5f*(v1z+v2z);
        float nx = v1y*v2z - v1z*v2y;
        float ny = v1z*v2x - v1x*v2z;
        float nz = v1x*v2y - v1y*v2x;
        float nrm = sqrtf(nx*nx + ny*ny + nz*nz);
        float inv = 1.f/(nrm + 1e-6f);
        nx *= inv; ny *= inv; nz *= inv;
        if (i == 0) sgn = (nx > 0.f) ? 1.f : -1.f;
        nx *= sgn; ny *= sgn; nz *= sgn;
        float pos = (nx*cx + ny*cy + nz*cz) * 0.57735026918962576f; // 1/sqrt(3)

        float f[7] = {cx, cy, cz, nx, ny, nz, pos};
        #pragma unroll
        for (int c = 0; c < 10; c++) {
            float h = sB1[c];
            #pragma unroll
            for (int ff = 0; ff < 7; ff++) h = fmaf(f[ff], sW1[ff*10 + c], h);
            g_h1[rowbase + i*10 + c] = h;
            sum[c] += h;
            sq[c]  = fmaf(h, h, sq[c]);
        }
    }

    // warp reduce -> per-warp smem -> per-block partials
    #pragma unroll
    for (int c = 0; c < 10; c++) {
        #pragma unroll
        for (int o = 16; o > 0; o >>= 1) {
            sum[c] += __shfl_down_sync(0xffffffffu, sum[c], o);
            sq[c]  += __shfl_down_sync(0xffffffffu, sq[c],  o);
        }
    }
    const int warp = threadIdx.x >> 5, lane = threadIdx.x & 31;
    if (lane == 0) {
        #pragma unroll
        for (int c = 0; c < 10; c++) {
            sRed[warp*20 + c]      = sum[c];
            sRed[warp*20 + 10 + c] = sq[c];
        }
    }
    __syncthreads();
    if (threadIdx.x < 20) {
        float t = 0.f;
        #pragma unroll
        for (int w = 0; w < TPB/32; w++) t += sRed[w*20 + threadIdx.x];
        g_part1[blockIdx.x*20 + threadIdx.x] = t;
    }
}

// =====================================================================
// Parallel BN-stats finalize (shared body)
// =====================================================================
__device__ __forceinline__ void fin_body(const float* __restrict__ part, int nblk,
                                         const float* __restrict__ g,
                                         const float* __restrict__ be,
                                         float* __restrict__ coef)
{
    __shared__ float red[32*20];
    __shared__ float tot[20];
    const int t = threadIdx.x;          // 640 threads
    const int c = t % 20, sub = t / 20; // 32 subs
    float acc = 0.f;
    for (int k = sub; k < nblk; k += 32) acc += part[k*20 + c];
    red[sub*20 + c] = acc;
    __syncthreads();
    if (t < 20) {
        float s = 0.f;
        #pragma unroll
        for (int w = 0; w < 32; w++) s += red[w*20 + t];
        tot[t] = s;
    }
    __syncthreads();
    if (t < 10) {
        float mu  = tot[t] / (float)NROWS;
        float var = tot[10 + t] / (float)NROWS - mu*mu;
        float a   = g[t] * rsqrtf(var + EPS_BN);
        coef[t]      = a;
        coef[10 + t] = be[t] - mu*a;
    }
}

__global__ void k_fin1(const float* __restrict__ g1, const float* __restrict__ be1)
{ fin_body(g_part1, NB1, g1, be1, g_coef1); }

__global__ void k_fin2(const float* __restrict__ g2, const float* __restrict__ be2)
{ fin_body(g_part2, NB3, g2, be2, g_coef2); }

// =====================================================================
// Kernel 3: BN1 + relu + GEMM2 + stats2
// =====================================================================
__global__ void __launch_bounds__(TPB) k_mlp2(const float* __restrict__ W2,
                                              const float* __restrict__ b2)
{
    __shared__ float sW2[100], sB2[10], sA[10], sC[10], sRed[(TPB/32)*20];
    const int t = threadIdx.x;
    if (t < 100) sW2[t] = W2[t];
    if (t < 10) { sB2[t] = b2[t]; sA[t] = g_coef1[t]; sC[t] = g_coef1[10+t]; }
    __syncthreads();

    const size_t row = (size_t)blockIdx.x*TPB + t;
    const float* src = g_h1 + row*10;

    float h[10];
    #pragma unroll
    for (int c = 0; c < 10; c++) h[c] = fmaxf(fmaf(src[c], sA[c], sC[c]), 0.f);

    float sum[10], sq[10];
    float* dst = g_h2 + row*10;
    #pragma unroll
    for (int c2 = 0; c2 < 10; c2++) {
        float z = sB2[c2];
        #pragma unroll
        for (int c = 0; c < 10; c++) z = fmaf(h[c], sW2[c*10 + c2], z);
        dst[c2] = z;
        sum[c2] = z;
        sq[c2]  = z*z;
    }

    #pragma unroll
    for (int c = 0; c < 10; c++) {
        #pragma unroll
        for (int o = 16; o > 0; o >>= 1) {
            sum[c] += __shfl_down_sync(0xffffffffu, sum[c], o);
            sq[c]  += __shfl_down_sync(0xffffffffu, sq[c],  o);
        }
    }
    const int warp = t >> 5, lane = t & 31;
    if (lane == 0) {
        #pragma unroll
        for (int c = 0; c < 10; c++) {
            sRed[warp*20 + c]      = sum[c];
            sRed[warp*20 + 10 + c] = sq[c];
        }
    }
    __syncthreads();
    if (t < 20) {
        float acc = 0.f;
        #pragma unroll
        for (int w = 0; w < TPB/32; w++) acc += sRed[w*20 + t];
        g_part2[blockIdx.x*20 + t] = acc;
    }
}

// =====================================================================
// Kernel 5: BN2 + relu + max over k
// =====================================================================
__global__ void __launch_bounds__(TPB) k_out(float* __restrict__ out)
{
    __shared__ float sA[10], sC[10];
    if (threadIdx.x < 10) { sA[threadIdx.x] = g_coef2[threadIdx.x]; sC[threadIdx.x] = g_coef2[10+threadIdx.x]; }
    __syncthreads();

    const size_t p = (size_t)blockIdx.x*TPB + threadIdx.x;    // global point
    const float* src = g_h2 + p*KNN*10;

    float mx[10];
    #pragma unroll
    for (int c = 0; c < 10; c++) mx[c] = 0.f;   // relu outputs are >= 0

    #pragma unroll
    for (int i = 0; i < KNN; i++) {
        #pragma unroll
        for (int c = 0; c < 10; c++) {
            float v = fmaxf(fmaf(src[i*10 + c], sA[c], sC[c]), 0.f);
            mx[c] = fmaxf(mx[c], v);
        }
    }
    float* o = out + p*10;
    #pragma unroll
    for (int c = 0; c < 10; c++) o[c] = mx[c];
}

// =====================================================================
extern "C" void kernel_launch(void* const* d_in, const int* in_sizes, int n_in,
                              void* d_out, int out_size)
{
    const float* x   = (const float*)d_in[0];
    const float* W1  = (const float*)d_in[1];
    const float* b1  = (const float*)d_in[2];
    const float* g1  = (const float*)d_in[3];
    const float* be1 = (const float*)d_in[4];
    const float* W2  = (const float*)d_in[5];
    const float* b2  = (const float*)d_in[6];
    const float* g2  = (const float*)d_in[7];
    const float* be2 = (const float*)d_in[8];
    float* out = (float*)d_out;

    const size_t smem1 = (size_t)NPTS*sizeof(float4) + (70 + 10 + (TPB/32)*20)*sizeof(float);
    cudaFuncSetAttribute(k_knn_feat, cudaFuncAttributeMaxDynamicSharedMemorySize, (int)smem1);

    k_knn_feat<<<NB1, TPB, smem1>>>(x, W1, b1);
    k_fin1<<<1, 640>>>(g1, be1);
    k_mlp2<<<NB3, TPB>>>(W2, b2);
    k_fin2<<<1, 640>>>(g2, be2);
    k_out<<<NPOINTS/TPB, TPB>>>(out);
}

// round 3
// speedup vs baseline: 1.4931x; 1.3325x over previous
#include <cuda_runtime.h>
#include <math.h>

#define B_    4
#define NPTS  8192
#define KNN   9
#define TPB   256
#define KTPB  512                 // knn kernel threads (256 queries x 2 halves)
#define QPB   256                 // queries per block
#define HALFN 4096                // candidates per half
#define CAP   12                  // phase-2 list capacity per half
#define NPOINTS (B_*NPTS)         // 32768
#define NROWS   (NPOINTS*KNN)     // 294912
#define NB1     (NPOINTS/QPB)     // 128
#define NB3     (NROWS/TPB)       // 1152
#define EPS_BN  1e-5f

// ---- scratch (static device memory; no allocations) ----
__device__ float g_h1[(size_t)NROWS*10];
__device__ float g_h2[(size_t)NROWS*10];
__device__ float g_part1[NB1*20];
__device__ float g_part2[NB3*20];
__device__ float g_coef1[20];
__device__ float g_coef2[20];

// ---- packed f32x2 helpers ----
__device__ __forceinline__ unsigned long long ffma2(unsigned long long a,
                                                    unsigned long long b,
                                                    unsigned long long c) {
    unsigned long long r;
    asm("fma.rn.f32x2 %0, %1, %2, %3;" : "=l"(r) : "l"(a), "l"(b), "l"(c));
    return r;
}
__device__ __forceinline__ unsigned long long pack2(float a, float b) {
    unsigned long long r;
    asm("mov.b64 %0, {%1, %2};" : "=l"(r) : "f"(a), "f"(b));
    return r;
}
__device__ __forceinline__ void unpack2(unsigned long long v, float& lo, float& hi) {
    asm("mov.b64 {%0, %1}, %2;" : "=f"(lo), "=f"(hi) : "l"(v));
}

// branchless insert of one value into sorted-ascending s[0..9]
#define CHAIN_INSERT(sarr, val) do {                 \
    float _c = (val);                                \
    _Pragma("unroll")                                \
    for (int _j = 0; _j < 10; _j++) {                \
        float _lo = fminf(sarr[_j], _c);             \
        _c = fmaxf(sarr[_j], _c);                    \
        sarr[_j] = _lo;                              \
    }                                                \
} while (0)

// =====================================================================
// Kernel 1: kNN (2-pass, split candidates across 2 threads/query)
//           + angular features + GEMM1 + stats
// =====================================================================
__global__ void __launch_bounds__(KTPB) k_knn_feat(const float* __restrict__ x,
                                                   const float* __restrict__ W1,
                                                   const float* __restrict__ b1)
{
    extern __shared__ unsigned char smem_raw[];
    float* spx  = (float*)smem_raw;          // [NPTS]
    float* spy  = spx + NPTS;
    float* spz  = spy + NPTS;
    float* spw  = spz + NPTS;
    float* sVal = spw + NPTS;                // [QPB*10]  hi-half partial top-10
    float* sThr = sVal + QPB*10;             // [QPB]
    float* sW1  = sThr + QPB;                // 70
    float* sB1  = sW1 + 70;                  // 10
    float* sRed = sB1 + 10;                  // 16*20
    int*   sList = (int*)(sRed + (KTPB/32)*20);  // [KTPB*CAP]
    int*   sCnt  = sList + KTPB*CAP;             // [KTPB]
    int*   sFin  = sCnt + KTPB;                  // [QPB*10]

    const int t    = threadIdx.x;
    const int half = t >> 8;           // 0 = lo candidates, 1 = hi
    const int ql   = t & 255;          // query-within-block
    const int b    = blockIdx.x >> 5;              // batch
    const int n    = (blockIdx.x & 31) * QPB + ql; // query within batch
    const float* xb = x + (size_t)b*NPTS*3;

    // SoA tile of whole batch
    for (int i = t; i < NPTS; i += KTPB) {
        float px = xb[3*i+0], py = xb[3*i+1], pz = xb[3*i+2];
        spx[i] = px; spy[i] = py; spz[i] = pz;
        spw[i] = px*px + py*py + pz*pz;
    }
    if (t < 70) sW1[t] = W1[t];
    if (t < 10) sB1[t] = b1[t];
    __syncthreads();

    const float qx = spx[n], qy = spy[n], qz = spz[n];
    const float nqx = qx * -2.0f, nqy = qy * -2.0f, nqz = qz * -2.0f;
    const unsigned long long pqx = pack2(nqx, nqx);
    const unsigned long long pqy = pack2(nqy, nqy);
    const unsigned long long pqz = pack2(nqz, nqz);

    const ulonglong2* X2 = (const ulonglong2*)spx;
    const ulonglong2* Y2 = (const ulonglong2*)spy;
    const ulonglong2* Z2 = (const ulonglong2*)spz;
    const ulonglong2* W2 = (const ulonglong2*)spw;

    const int mbase = half * HALFN;

    // ---------------- phase 1: values-only top-10 over this half --------
    float s[10];
    #pragma unroll
    for (int j = 0; j < 10; j++) s[j] = 3.4e38f;

    #pragma unroll 1
    for (int m0 = mbase; m0 < mbase + HALFN; m0 += 8) {
        const int e = m0 >> 2;
        ulonglong2 xa = X2[e], xb2 = X2[e+1];
        ulonglong2 ya = Y2[e], yb = Y2[e+1];
        ulonglong2 za = Z2[e], zb = Z2[e+1];
        ulonglong2 wa = W2[e], wb = W2[e+1];
        unsigned long long d01 = ffma2(xa.x, pqx, wa.x);
        unsigned long long d23 = ffma2(xa.y, pqx, wa.y);
        unsigned long long d45 = ffma2(xb2.x, pqx, wb.x);
        unsigned long long d67 = ffma2(xb2.y, pqx, wb.y);
        d01 = ffma2(ya.x, pqy, d01);  d23 = ffma2(ya.y, pqy, d23);
        d45 = ffma2(yb.x, pqy, d45);  d67 = ffma2(yb.y, pqy, d67);
        d01 = ffma2(za.x, pqz, d01);  d23 = ffma2(za.y, pqz, d23);
        d45 = ffma2(zb.x, pqz, d45);  d67 = ffma2(zb.y, pqz, d67);
        float d0,d1,d2,d3,d4,d5,d6,d7;
        unpack2(d01, d0, d1); unpack2(d23, d2, d3);
        unpack2(d45, d4, d5); unpack2(d67, d6, d7);
        float mn = fminf(fminf(fminf(d0,d1), fminf(d2,d3)),
                         fminf(fminf(d4,d5), fminf(d6,d7)));
        if (mn < s[9]) {
            if (d0 < s[9]) CHAIN_INSERT(s, d0);
            if (d1 < s[9]) CHAIN_INSERT(s, d1);
            if (d2 < s[9]) CHAIN_INSERT(s, d2);
            if (d3 < s[9]) CHAIN_INSERT(s, d3);
            if (d4 < s[9]) CHAIN_INSERT(s, d4);
            if (d5 < s[9]) CHAIN_INSERT(s, d5);
            if (d6 < s[9]) CHAIN_INSERT(s, d6);
            if (d7 < s[9]) CHAIN_INSERT(s, d7);
        }
    }

    // ---------------- merge halves -> exact threshold -------------------
    if (half == 1) {
        #pragma unroll
        for (int j = 0; j < 10; j++) sVal[ql*10 + j] = s[j];
    }
    __syncthreads();
    float thr, gmin = 0.f;
    if (half == 0) {
        #pragma unroll
        for (int j = 0; j < 10; j++) {
            float v = sVal[ql*10 + j];
            CHAIN_INSERT(s, v);
        }
        thr = s[9]; gmin = s[0];
        sThr[ql] = thr;
    }
    __syncthreads();
    if (half == 1) thr = sThr[ql];

    // ---------------- phase 2: collect qualifying ids (index order) -----
    int cnt = 0;
    int* myList = sList + t*CAP;
    #pragma unroll 1
    for (int m0 = mbase; m0 < mbase + HALFN; m0 += 8) {
        const int e = m0 >> 2;
        ulonglong2 xa = X2[e], xb2 = X2[e+1];
        ulonglong2 ya = Y2[e], yb = Y2[e+1];
        ulonglong2 za = Z2[e], zb = Z2[e+1];
        ulonglong2 wa = W2[e], wb = W2[e+1];
        unsigned long long d01 = ffma2(xa.x, pqx, wa.x);
        unsigned long long d23 = ffma2(xa.y, pqx, wa.y);
        unsigned long long d45 = ffma2(xb2.x, pqx, wb.x);
        unsigned long long d67 = ffma2(xb2.y, pqx, wb.y);
        d01 = ffma2(ya.x, pqy, d01);  d23 = ffma2(ya.y, pqy, d23);
        d45 = ffma2(yb.x, pqy, d45);  d67 = ffma2(yb.y, pqy, d67);
        d01 = ffma2(za.x, pqz, d01);  d23 = ffma2(za.y, pqz, d23);
        d45 = ffma2(zb.x, pqz, d45);  d67 = ffma2(zb.y, pqz, d67);
        float dv[8];
        unpack2(d01, dv[0], dv[1]); unpack2(d23, dv[2], dv[3]);
        unpack2(d45, dv[4], dv[5]); unpack2(d67, dv[6], dv[7]);
        float mn = fminf(fminf(fminf(dv[0],dv[1]), fminf(dv[2],dv[3])),
                         fminf(fminf(dv[4],dv[5]), fminf(dv[6],dv[7])));
        if (mn <= thr) {
            #pragma unroll
            for (int u = 0; u < 8; u++) {
                if (dv[u] <= thr && cnt < CAP) { myList[cnt] = m0 + u; cnt++; }
            }
        }
    }
    sCnt[t] = cnt;
    __syncthreads();

    // ---------------- selection + features + GEMM1 (lo threads only) ----
    float sum[10], sq[10];
    #pragma unroll
    for (int c = 0; c < 10; c++) { sum[c] = 0.f; sq[c] = 0.f; }

    if (half == 0) {
        const int c0 = sCnt[ql], c1 = sCnt[ql + 256];
        const int* l0 = sList + ql*CAP;
        const int* l1 = sList + (ql + 256)*CAP;
        int np = 0;
        // pass A: strictly below threshold, index order
        for (int h = 0; h < 2; h++) {
            const int* L = h ? l1 : l0;
            const int  C = h ? c1 : c0;
            for (int j = 0; j < C; j++) {
                int id = L[j];
                float v = fmaf(spx[id], nqx, spw[id]);
                v = fmaf(spy[id], nqy, v);
                v = fmaf(spz[id], nqz, v);
                if (v < thr) { sFin[ql*10 + np] = id; np++; }
            }
        }
        // pass B: ties at threshold fill remaining slots, index order
        for (int h = 0; h < 2; h++) {
            const int* L = h ? l1 : l0;
            const int  C = h ? c1 : c0;
            for (int j = 0; j < C; j++) {
                int id = L[j];
                float v = fmaf(spx[id], nqx, spw[id]);
                v = fmaf(spy[id], nqy, v);
                v = fmaf(spz[id], nqz, v);
                if (v == thr && np < 10) { sFin[ql*10 + np] = id; np++; }
            }
        }
        // find the top_k-first entry (global min value, lowest index) to drop
        int pos = 0;
        {
            bool found = false;
            #pragma unroll
            for (int j = 0; j < 10; j++) {
                int id = sFin[ql*10 + j];
                float v = fmaf(spx[id], nqx, spw[id]);
                v = fmaf(spy[id], nqy, v);
                v = fmaf(spz[id], nqz, v);
                if (!found && v == gmin) { pos = j; found = true; }
            }
        }

        // 9 neighbors, relative vectors + angle
        float rx[KNN], ry[KNN], rz[KNN], ph[KNN];
        #pragma unroll
        for (int j = 0; j < KNN; j++) {
            int srcj = j + (j >= pos ? 1 : 0);
            int id = sFin[ql*10 + srcj];
            rx[j] = spx[id] - qx; ry[j] = spy[id] - qy; rz[j] = spz[id] - qz;
            ph[j] = atan2f(ry[j], rx[j]);
        }

        // stable ascending sort by phi
        #pragma unroll
        for (int pass = 0; pass < KNN-1; pass++) {
            #pragma unroll
            for (int j = 0; j < KNN-1; j++) {
                if (j < KNN-1-pass) {
                    if (ph[j+1] < ph[j]) {
                        float tt;
                        tt = ph[j]; ph[j] = ph[j+1]; ph[j+1] = tt;
                        tt = rx[j]; rx[j] = rx[j+1]; rx[j+1] = tt;
                        tt = ry[j]; ry[j] = ry[j+1]; ry[j+1] = tt;
                        tt = rz[j]; rz[j] = rz[j+1]; rz[j+1] = tt;
                    }
                }
            }
        }

        float sgn = 1.f;
        const size_t rowbase = ((size_t)(b*NPTS + n) * KNN) * 10;
        #pragma unroll
        for (int i = 0; i < KNN; i++) {
            const int i2 = (i+1) % KNN;
            float v1x = rx[i],  v1y = ry[i],  v1z = rz[i];
            float v2x = rx[i2], v2y = ry[i2], v2z = rz[i2];
            float cx = 0.5f*(v1x+v2x), cy = 0.5f*(v1y+v2y), cz = 0.5f*(v1z+v2z);
            float nx = v1y*v2z - v1z*v2y;
            float ny = v1z*v2x - v1x*v2z;
            float nz = v1x*v2y - v1y*v2x;
            float nrm = sqrtf(nx*nx + ny*ny + nz*nz);
            float inv = 1.f/(nrm + 1e-6f);
            nx *= inv; ny *= inv; nz *= inv;
            if (i == 0) sgn = (nx > 0.f) ? 1.f : -1.f;
            nx *= sgn; ny *= sgn; nz *= sgn;
            float pos7 = (nx*cx + ny*cy + nz*cz) * 0.57735026918962576f;

            float f[7] = {cx, cy, cz, nx, ny, nz, pos7};
            #pragma unroll
            for (int c = 0; c < 10; c++) {
                float h = sB1[c];
                #pragma unroll
                for (int ff = 0; ff < 7; ff++) h = fmaf(f[ff], sW1[ff*10 + c], h);
                g_h1[rowbase + i*10 + c] = h;
                sum[c] += h;
                sq[c]  = fmaf(h, h, sq[c]);
            }
        }
    }

    // block reduction of stats (all 16 warps; hi warps contribute zeros)
    #pragma unroll
    for (int c = 0; c < 10; c++) {
        #pragma unroll
        for (int o = 16; o > 0; o >>= 1) {
            sum[c] += __shfl_down_sync(0xffffffffu, sum[c], o);
            sq[c]  += __shfl_down_sync(0xffffffffu, sq[c],  o);
        }
    }
    const int warp = t >> 5, lane = t & 31;
    if (lane == 0) {
        #pragma unroll
        for (int c = 0; c < 10; c++) {
            sRed[warp*20 + c]      = sum[c];
            sRed[warp*20 + 10 + c] = sq[c];
        }
    }
    __syncthreads();
    if (t < 20) {
        float acc = 0.f;
        #pragma unroll
        for (int w = 0; w < KTPB/32; w++) acc += sRed[w*20 + t];
        g_part1[blockIdx.x*20 + t] = acc;
    }
}

// =====================================================================
// Parallel BN-stats finalize (shared body)
// =====================================================================
__device__ __forceinline__ void fin_body(const float* __restrict__ part, int nblk,
                                         const float* __restrict__ g,
                                         const float* __restrict__ be,
                                         float* __restrict__ coef)
{
    __shared__ float red[32*20];
    __shared__ float tot[20];
    const int t = threadIdx.x;          // 640 threads
    const int c = t % 20, sub = t / 20; // 32 subs
    float acc = 0.f;
    for (int k = sub; k < nblk; k += 32) acc += part[k*20 + c];
    red[sub*20 + c] = acc;
    __syncthreads();
    if (t < 20) {
        float s = 0.f;
        #pragma unroll
        for (int w = 0; w < 32; w++) s += red[w*20 + t];
        tot[t] = s;
    }
    __syncthreads();
    if (t < 10) {
        float mu  = tot[t] / (float)NROWS;
        float var = tot[10 + t] / (float)NROWS - mu*mu;
        float a   = g[t] * rsqrtf(var + EPS_BN);
        coef[t]      = a;
        coef[10 + t] = be[t] - mu*a;
    }
}

__global__ void k_fin1(const float* __restrict__ g1, const float* __restrict__ be1)
{ fin_body(g_part1, NB1, g1, be1, g_coef1); }

__global__ void k_fin2(const float* __restrict__ g2, const float* __restrict__ be2)
{ fin_body(g_part2, NB3, g2, be2, g_coef2); }

// =====================================================================
// Kernel 3: BN1 + relu + GEMM2 + stats2
// =====================================================================
__global__ void __launch_bounds__(TPB) k_mlp2(const float* __restrict__ W2,
                                              const float* __restrict__ b2)
{
    __shared__ float sW2[100], sB2[10], sA[10], sC[10], sRed[(TPB/32)*20];
    const int t = threadIdx.x;
    if (t < 100) sW2[t] = W2[t];
    if (t < 10) { sB2[t] = b2[t]; sA[t] = g_coef1[t]; sC[t] = g_coef1[10+t]; }
    __syncthreads();

    const size_t row = (size_t)blockIdx.x*TPB + t;
    const float* src = g_h1 + row*10;

    float h[10];
    #pragma unroll
    for (int c = 0; c < 10; c++) h[c] = fmaxf(fmaf(src[c], sA[c], sC[c]), 0.f);

    float sum[10], sq[10];
    float* dst = g_h2 + row*10;
    #pragma unroll
    for (int c2 = 0; c2 < 10; c2++) {
        float z = sB2[c2];
        #pragma unroll
        for (int c = 0; c < 10; c++) z = fmaf(h[c], sW2[c*10 + c2], z);
        dst[c2] = z;
        sum[c2] = z;
        sq[c2]  = z*z;
    }

    #pragma unroll
    for (int c = 0; c < 10; c++) {
        #pragma unroll
        for (int o = 16; o > 0; o >>= 1) {
            sum[c] += __shfl_down_sync(0xffffffffu, sum[c], o);
            sq[c]  += __shfl_down_sync(0xffffffffu, sq[c],  o);
        }
    }
    const int warp = t >> 5, lane = t & 31;
    if (lane == 0) {
        #pragma unroll
        for (int c = 0; c < 10; c++) {
            sRed[warp*20 + c]      = sum[c];
            sRed[warp*20 + 10 + c] = sq[c];
        }
    }
    __syncthreads();
    if (t < 20) {
        float acc = 0.f;
        #pragma unroll
        for (int w = 0; w < TPB/32; w++) acc += sRed[w*20 + t];
        g_part2[blockIdx.x*20 + t] = acc;
    }
}

// =====================================================================
// Kernel 5: BN2 + relu + max over k
// =====================================================================
__global__ void __launch_bounds__(TPB) k_out(float* __restrict__ out)
{
    __shared__ float sA[10], sC[10];
    if (threadIdx.x < 10) { sA[threadIdx.x] = g_coef2[threadIdx.x]; sC[threadIdx.x] = g_coef2[10+threadIdx.x]; }
    __syncthreads();

    const size_t p = (size_t)blockIdx.x*TPB + threadIdx.x;
    const float* src = g_h2 + p*KNN*10;

    float mx[10];
    #pragma unroll
    for (int c = 0; c < 10; c++) mx[c] = 0.f;

    #pragma unroll
    for (int i = 0; i < KNN; i++) {
        #pragma unroll
        for (int c = 0; c < 10; c++) {
            float v = fmaxf(fmaf(src[i*10 + c], sA[c], sC[c]), 0.f);
            mx[c] = fmaxf(mx[c], v);
        }
    }
    float* o = out + p*10;
    #pragma unroll
    for (int c = 0; c < 10; c++) o[c] = mx[c];
}

// =====================================================================
extern "C" void kernel_launch(void* const* d_in, const int* in_sizes, int n_in,
                              void* d_out, int out_size)
{
    const float* x   = (const float*)d_in[0];
    const float* W1  = (const float*)d_in[1];
    const float* b1  = (const float*)d_in[2];
    const float* g1  = (const float*)d_in[3];
    const float* be1 = (const float*)d_in[4];
    const float* W2  = (const float*)d_in[5];
    const float* b2  = (const float*)d_in[6];
    const float* g2  = (const float*)d_in[7];
    const float* be2 = (const float*)d_in[8];
    float* out = (float*)d_out;

    const size_t smem1 =
        (size_t)(4*NPTS + QPB*10 + QPB + 70 + 10 + (KTPB/32)*20) * sizeof(float)
        + (size_t)(KTPB*CAP + KTPB + QPB*10) * sizeof(int);
    cudaFuncSetAttribute(k_knn_feat, cudaFuncAttributeMaxDynamicSharedMemorySize, (int)smem1);

    k_knn_feat<<<NB1, KTPB, smem1>>>(x, W1, b1);
    k_fin1<<<1, 640>>>(g1, be1);
    k_mlp2<<<NB3, TPB>>>(W2, b2);
    k_fin2<<<1, 640>>>(g2, be2);
    k_out<<<NPOINTS/TPB, TPB>>>(out);
}